// round 14
// baseline (speedup 1.0000x reference)
#include <cuda_runtime.h>
#include <cuda_fp16.h>
#include <cstdint>
#include <math.h>

// ---------------- problem constants ----------------
#define B_    4096
#define IN_   2048
#define H_    2048

// Single-pass fp16: gates ~= fp16(A) x fp16(W).  K = 4096 = 64 chunks of 4 k16.
#define NCHUNK 64
#define STAGES 3

#define MBLK 32               // 4096/128
#define NBLK 64               // 8192/128
#define NPACK 96              // packer CTAs: 32 A + 64 B (all in wave 1)

// gmem fragment-layout blocks
// A: [mblk][kc 256][m16 8][lane 32]{uint4}
// B: [nblk][kc 256][n8pair 8][lane 32]{uint2 x2}
__device__ uint4 g_A[(size_t)MBLK * 256 * 8 * 32];
__device__ uint2 g_B[(size_t)NBLK * 256 * 8 * 32 * 2];

// per-pipeline-chunk readiness flags
__device__ int g_flagA[MBLK * NCHUNK];   // 2048
__device__ int g_flagB[NBLK * NCHUNK];   // 4096

#define A_STAGE_BYTES 16384   // 4 k16 * 8 m16 * 512B
#define B_STAGE_BYTES 16384   // 4 k16 * 8 n8pair * 512B
#define STAGE_BYTES   (A_STAGE_BYTES + B_STAGE_BYTES)   // 32768
#define SMEM_REQ      (STAGES * STAGE_BYTES)            // 98304

// ---------------- PTX helpers ----------------
__device__ __forceinline__ uint32_t smem_u32(const void* p) {
    uint32_t a;
    asm("{ .reg .u64 t; cvta.to.shared.u64 t, %1; cvt.u32.u64 %0, t; }" : "=r"(a) : "l"(p));
    return a;
}
#define MBAR_INIT(a, n) asm volatile("mbarrier.init.shared.b64 [%0], %1;" :: "r"(a), "r"(n) : "memory")
#define MBAR_EXPECT_TX(a, b) asm volatile("mbarrier.arrive.expect_tx.shared.b64 _, [%0], %1;" :: "r"(a), "r"(b) : "memory")

__device__ __forceinline__ void mbar_wait(uint32_t mbar, uint32_t parity) {
    asm volatile(
        "{\n\t.reg .pred P;\n\t"
        "WL_%=:\n\t"
        "mbarrier.try_wait.parity.acquire.cta.shared::cta.b64 P, [%0], %1, 0x989680;\n\t"
        "@P bra.uni WD_%=;\n\t"
        "bra.uni WL_%=;\n\t"
        "WD_%=:\n\t}"
        :: "r"(mbar), "r"(parity) : "memory");
}
__device__ __forceinline__ void bulk_cp(uint32_t dst, const void* src, uint32_t bytes, uint32_t mbar) {
    asm volatile(
        "cp.async.bulk.shared::cluster.global.mbarrier::complete_tx::bytes [%0], [%1], %2, [%3];"
        :: "r"(dst), "l"(src), "r"(bytes), "r"(mbar) : "memory");
}
__device__ __forceinline__ void mma16816(float* c, const uint32_t* a, const uint32_t* b) {
    asm volatile(
        "mma.sync.aligned.m16n8k16.row.col.f32.f16.f16.f32 "
        "{%0,%1,%2,%3}, {%4,%5,%6,%7}, {%8,%9}, {%0,%1,%2,%3};"
        : "+f"(c[0]), "+f"(c[1]), "+f"(c[2]), "+f"(c[3])
        : "r"(a[0]), "r"(a[1]), "r"(a[2]), "r"(a[3]), "r"(b[0]), "r"(b[1]));
}
__device__ __forceinline__ float tanh_fast(float x) {
    float y;
    asm("tanh.approx.f32 %0, %1;" : "=f"(y) : "f"(x));
    return y;
}
__device__ __forceinline__ float sigmoid_fast(float x) {
    return fmaf(tanh_fast(0.5f * x), 0.5f, 0.5f);
}
__device__ __forceinline__ void flag_set(int* p) {
    asm volatile("st.release.gpu.global.u32 [%0], %1;" :: "l"(p), "r"(1u) : "memory");
}
__device__ __forceinline__ void flag_wait(const int* p) {
    uint32_t v;
    asm volatile("ld.acquire.gpu.global.u32 %0, [%1];" : "=r"(v) : "l"(p) : "memory");
    while (v == 0) {
        asm volatile("nanosleep.u32 128;");
        asm volatile("ld.acquire.gpu.global.u32 %0, [%1];" : "=r"(v) : "l"(p) : "memory");
    }
}
__device__ __forceinline__ uint32_t pack2h(float v0, float v1) {
    __half h0 = __float2half_rn(v0);
    __half h1 = __float2half_rn(v1);
    uint16_t u0 = *(uint16_t*)&h0, u1 = *(uint16_t*)&h1;
    return (uint32_t)u0 | ((uint32_t)u1 << 16);
}

// ---------------- flags reset ----------------
__global__ __launch_bounds__(256) void reset_flags() {
    int i = blockIdx.x * 256 + threadIdx.x;   // 24 * 256 = 6144
    if (i < MBLK * NCHUNK) g_flagA[i] = 0;
    if (i < NBLK * NCHUNK) g_flagB[i] = 0;
}

// ---------------- fused pack + GEMM + LSTM ----------------
__global__ __launch_bounds__(128, 2) void lstm_gemm_kernel(
    const float* __restrict__ x,   const float* __restrict__ hin,
    const float* __restrict__ c_prev,
    const float* __restrict__ Wxi, const float* __restrict__ Wxo,
    const float* __restrict__ Wxf, const float* __restrict__ Wxc,
    const float* __restrict__ bi,  const float* __restrict__ bo,
    const float* __restrict__ bfv, const float* __restrict__ bc,
    const float* __restrict__ Whi, const float* __restrict__ Who,
    const float* __restrict__ Whf, const float* __restrict__ Whc,
    float* __restrict__ out_h, float* __restrict__ out_c)
{
    extern __shared__ __align__(1024) unsigned char smem_raw[];
    __shared__ __align__(8) uint64_t mbar_full[STAGES];

    const int tid  = threadIdx.x;
    const int wid  = tid >> 5;
    const int lane = tid & 31;
    const int warp_m = wid & 1;
    const int warp_n = wid >> 1;
    const int by = blockIdx.x;      // mblk 0..31
    const int bx = blockIdx.y;      // nblk 0..63
    const int bid = by + bx * 32;   // linear id; bids 0..95 are wave-1 packers

    const uint32_t sbase = smem_u32(smem_raw);
    uint32_t full[STAGES];
#pragma unroll
    for (int s = 0; s < STAGES; s++) full[s] = smem_u32(&mbar_full[s]);

    if (tid == 0) {
#pragma unroll
        for (int s = 0; s < STAGES; s++) MBAR_INIT(full[s], 1);
    }
    __syncthreads();

    const int g = lane >> 2, t = lane & 3;

    // ================= packer duty (bids 0..95, wave-1 resident) =================
    if (bid < NPACK) {
        if (bid < 32) {
            // ---- A packer: mblk = bid, all 64 pipeline chunks ----
            const int mblk = bid;
            for (int nc = 0; nc < NCHUNK; nc++) {
#pragma unroll
                for (int kk = 0; kk < 4; kk++) {
                    const int kc = nc * 4 + kk;
                    const int kb = kc * 16;
                    const float* src  = (kc < 128) ? x : hin;
                    const int    col0 = kb & 2047;
#pragma unroll
                    for (int mh = 0; mh < 2; mh++) {
                        const int m16 = wid + mh * 4;
                        const int r0 = mblk * 128 + m16 * 16 + g;
                        const float* p0 = src + (size_t)r0 * 2048 + col0;
                        const float* p1 = p0 + (size_t)8 * 2048;
                        float2 f00 = *(const float2*)(p0 + 2 * t);
                        float2 f01 = *(const float2*)(p0 + 2 * t + 8);
                        float2 f10 = *(const float2*)(p1 + 2 * t);
                        float2 f11 = *(const float2*)(p1 + 2 * t + 8);
                        uint4 out;
                        out.x = pack2h(f00.x, f00.y);
                        out.y = pack2h(f10.x, f10.y);
                        out.z = pack2h(f01.x, f01.y);
                        out.w = pack2h(f11.x, f11.y);
                        g_A[((size_t)(mblk * 256 + kc) * 8 + m16) * 32 + lane] = out;
                    }
                }
                __threadfence();
                __syncthreads();
                if (tid == 0) flag_set(&g_flagA[mblk * NCHUNK + nc]);
            }
        } else {
            // ---- B packer: nblk = bid-32, all 64 pipeline chunks ----
            const int nblk = bid - 32;
            const float* sx[4];
            const float* sh[4];
            int jv[4];
#pragma unroll
            for (int v = 0; v < 4; v++) {
                const int n8 = wid + v * 4;
                const int p = nblk * 128 + n8 * 8 + g;
                const int gate = (p >> 3) & 3;
                jv[v] = (p >> 5) * 8 + (p & 7);
                sx[v] = (gate == 0) ? Wxi : (gate == 1) ? Wxo : (gate == 2) ? Wxf : Wxc;
                sh[v] = (gate == 0) ? Whi : (gate == 1) ? Who : (gate == 2) ? Whf : Whc;
            }
            for (int nc = 0; nc < NCHUNK; nc++) {
#pragma unroll
                for (int kk = 0; kk < 4; kk++) {
                    const int kc = nc * 4 + kk;
                    const int kb = kc * 16;
                    const bool useX = (kc < 128);
                    const int col0 = kb & 2047;
#pragma unroll
                    for (int v = 0; v < 4; v++) {
                        const int n8 = wid + v * 4;
                        const float* src = useX ? sx[v] : sh[v];
                        const float* pr = src + (size_t)jv[v] * 2048 + col0;
                        float2 f0 = *(const float2*)(pr + 2 * t);
                        float2 f1 = *(const float2*)(pr + 2 * t + 8);
                        uint2 out;
                        out.x = pack2h(f0.x, f0.y);
                        out.y = pack2h(f1.x, f1.y);
                        g_B[(((size_t)(nblk * 256 + kc) * 8 + (n8 >> 1)) * 32 + lane) * 2 + (n8 & 1)] = out;
                    }
                }
                __threadfence();
                __syncthreads();
                if (tid == 0) flag_set(&g_flagB[nblk * NCHUNK + nc]);
            }
        }
    }

    // ================= GEMM =================
    const uint4* Abase = g_A + (size_t)by * 256 * 8 * 32;
    const uint4* Bbase = (const uint4*)g_B + (size_t)bx * 256 * 8 * 32;

    // prologue: fill stages (chunks 0..2), gated on pack flags
    if (tid == 0) {
#pragma unroll
        for (int s = 0; s < STAGES; s++) {
            flag_wait(&g_flagA[by * NCHUNK + s]);
            flag_wait(&g_flagB[bx * NCHUNK + s]);
            asm volatile("fence.proxy.async;" ::: "memory");
            MBAR_EXPECT_TX(full[s], STAGE_BYTES);
            bulk_cp(sbase + s * STAGE_BYTES,
                    Abase + (size_t)s * 1024, A_STAGE_BYTES, full[s]);
            bulk_cp(sbase + s * STAGE_BYTES + A_STAGE_BYTES,
                    Bbase + (size_t)s * 1024, B_STAGE_BYTES, full[s]);
        }
    }

    float acc[4][8][4];
#pragma unroll
    for (int mm = 0; mm < 4; mm++)
#pragma unroll
        for (int nn = 0; nn < 8; nn++)
#pragma unroll
            for (int q = 0; q < 4; q++) acc[mm][nn][q] = 0.0f;

    for (int i = 0; i < NCHUNK; i++) {
        const int s = i % STAGES;
        const uint32_t ph = (i / STAGES) & 1;
        mbar_wait(full[s], ph);

        const unsigned char* stA = smem_raw + s * STAGE_BYTES;
        const unsigned char* stB = stA + A_STAGE_BYTES;

#pragma unroll
        for (int k16 = 0; k16 < 4; k16++) {
            uint32_t a[4][4];
            uint32_t b[8][2];
#pragma unroll
            for (int mm = 0; mm < 4; mm++) {
                const uint4 v = *(const uint4*)(stA + ((k16 * 8 + warp_m * 4 + mm) * 32 + lane) * 16);
                a[mm][0] = v.x; a[mm][1] = v.y; a[mm][2] = v.z; a[mm][3] = v.w;
            }
#pragma unroll
            for (int np = 0; np < 4; np++) {
                const uint4 v = *(const uint4*)(stB + ((k16 * 8 + warp_n * 4 + np) * 32 + lane) * 16);
                b[np*2+0][0] = v.x; b[np*2+0][1] = v.y;
                b[np*2+1][0] = v.z; b[np*2+1][1] = v.w;
            }
#pragma unroll
            for (int mm = 0; mm < 4; mm++)
#pragma unroll
                for (int nn = 0; nn < 8; nn++)
                    mma16816(acc[mm][nn], a[mm], b[nn]);
        }

        __syncthreads();   // stage s fully consumed by all warps

        if (tid == 0 && i + STAGES < NCHUNK) {
            const int nc = i + STAGES;
            flag_wait(&g_flagA[by * NCHUNK + nc]);
            flag_wait(&g_flagB[bx * NCHUNK + nc]);
            asm volatile("fence.proxy.async;" ::: "memory");
            MBAR_EXPECT_TX(full[s], STAGE_BYTES);
            bulk_cp(sbase + s * STAGE_BYTES,
                    Abase + (size_t)nc * 1024, A_STAGE_BYTES, full[s]);
            bulk_cp(sbase + s * STAGE_BYTES + A_STAGE_BYTES,
                    Bbase + (size_t)nc * 1024, B_STAGE_BYTES, full[s]);
        }
    }

    // ---------------- fused LSTM epilogue (MUFU-minimal) ----------------
#pragma unroll
    for (int gg = 0; gg < 2; gg++) {
        const int j0 = (bx * 4 + warp_n * 2 + gg) * 8 + 2 * t;
        const float2 bi2 = *(const float2*)&bi[j0];
        const float2 bo2 = *(const float2*)&bo[j0];
        const float2 bf2 = *(const float2*)&bfv[j0];
        const float2 bc2v = *(const float2*)&bc[j0];

#pragma unroll
        for (int mm = 0; mm < 4; mm++) {
#pragma unroll
            for (int rr = 0; rr < 2; rr++) {
                const int m = by * 128 + warp_m * 64 + mm * 16 + g + rr * 8;
                const size_t base = (size_t)m * H_ + j0;
                const float2 cp = *(const float2*)&c_prev[base];

                float nh[2], ncv[2];
#pragma unroll
                for (int jj = 0; jj < 2; jj++) {
                    const int q = rr * 2 + jj;
                    const float gi = acc[mm][gg*4+0][q] + (jj ? bi2.y : bi2.x);
                    const float go = acc[mm][gg*4+1][q] + (jj ? bo2.y : bo2.x);
                    const float gf = acc[mm][gg*4+2][q] + (jj ? bf2.y : bf2.x);
                    const float gc = acc[mm][gg*4+3][q] + (jj ? bc2v.y : bc2v.x);

                    const float it = sigmoid_fast(gi);
                    const float ot = sigmoid_fast(go);
                    const float ft = sigmoid_fast(gf);
                    const float ct = tanh_fast(gc);

                    const float cold = jj ? cp.y : cp.x;
                    const float nc2 = ft * cold + it * ct;
                    ncv[jj] = nc2;
                    nh[jj]  = ot * tanh_fast(nc2);
                }
                *(float2*)&out_c[base] = make_float2(ncv[0], ncv[1]);
                *(float2*)&out_h[base] = make_float2(nh[0], nh[1]);
            }
        }
    }
}

// ---------------- launch ----------------
extern "C" void kernel_launch(void* const* d_in, const int* in_sizes, int n_in,
                              void* d_out, int out_size) {
    const float* x   = (const float*)d_in[0];
    const float* h   = (const float*)d_in[1];
    const float* c   = (const float*)d_in[2];
    const float* Wxi = (const float*)d_in[3];
    const float* Wxo = (const float*)d_in[4];
    const float* Wxf = (const float*)d_in[5];
    const float* Wxc = (const float*)d_in[6];
    const float* bi  = (const float*)d_in[7];
    const float* bo  = (const float*)d_in[8];
    const float* bfv = (const float*)d_in[9];
    const float* bc  = (const float*)d_in[10];
    const float* Whi = (const float*)d_in[11];
    const float* Who = (const float*)d_in[12];
    const float* Whf = (const float*)d_in[13];
    const float* Whc = (const float*)d_in[14];

    float* out   = (float*)d_out;
    float* out_h = out;
    float* out_c = out + (size_t)B_ * H_;

    static bool attr_set = false;
    if (!attr_set) {
        cudaFuncSetAttribute(lstm_gemm_kernel,
                             cudaFuncAttributeMaxDynamicSharedMemorySize, SMEM_REQ);
        attr_set = true;
    }

    reset_flags<<<24, 256>>>();

    dim3 grid(MBLK, NBLK);   // (32, 64)
    lstm_gemm_kernel<<<grid, 128, SMEM_REQ>>>(x, h, c,
                                              Wxi, Wxo, Wxf, Wxc,
                                              bi, bo, bfv, bc,
                                              Whi, Who, Whf, Whc,
                                              out_h, out_c);
}

// round 15
// speedup vs baseline: 1.5617x; 1.5617x over previous
#include <cuda_runtime.h>
#include <cuda_fp16.h>
#include <cstdint>
#include <math.h>

// ---------------- problem constants ----------------
#define B_    4096
#define IN_   2048
#define H_    2048

// Single-pass fp16: gates ~= fp16(A) x fp16(W).  K = 4096 = 64 chunks of 4 k16.
#define NCHUNK 64
#define STAGES 3

#define MBLK 32               // 4096/128
#define NBLK 64               // 8192/128

// gmem fragment-layout blocks
// A: [mblk][kc 256][m16 8][lane 32]{uint4}
// B: [nblk][kc 256][n8pair 8][lane 32]{uint2 x2}
__device__ uint4 g_A[(size_t)MBLK * 256 * 8 * 32];
__device__ uint2 g_B[(size_t)NBLK * 256 * 8 * 32 * 2];

#define A_STAGE_BYTES 16384   // 4 k16 * 8 m16 * 512B
#define B_STAGE_BYTES 16384   // 4 k16 * 8 n8pair * 512B
#define STAGE_BYTES   (A_STAGE_BYTES + B_STAGE_BYTES)   // 32768
#define SMEM_REQ      (STAGES * STAGE_BYTES)            // 98304

// 4 kc per thread. A: one n-col set per thread; B: one adjacent n8-pair per thread.
#define A_PACK_BLOCKS ((MBLK * 64 * 8 * 32) / 256)      // 2048
#define B_PACK_BLOCKS ((NBLK * 64 * 8 * 32) / 256)      // 4096

// ---------------- PTX helpers ----------------
__device__ __forceinline__ uint32_t smem_u32(const void* p) {
    uint32_t a;
    asm("{ .reg .u64 t; cvta.to.shared.u64 t, %1; cvt.u32.u64 %0, t; }" : "=r"(a) : "l"(p));
    return a;
}
#define MBAR_INIT(a, n) asm volatile("mbarrier.init.shared.b64 [%0], %1;" :: "r"(a), "r"(n) : "memory")
#define MBAR_EXPECT_TX(a, b) asm volatile("mbarrier.arrive.expect_tx.shared.b64 _, [%0], %1;" :: "r"(a), "r"(b) : "memory")

__device__ __forceinline__ void mbar_wait(uint32_t mbar, uint32_t parity) {
    asm volatile(
        "{\n\t.reg .pred P;\n\t"
        "WL_%=:\n\t"
        "mbarrier.try_wait.parity.acquire.cta.shared::cta.b64 P, [%0], %1, 0x989680;\n\t"
        "@P bra.uni WD_%=;\n\t"
        "bra.uni WL_%=;\n\t"
        "WD_%=:\n\t}"
        :: "r"(mbar), "r"(parity) : "memory");
}
__device__ __forceinline__ void bulk_cp(uint32_t dst, const void* src, uint32_t bytes, uint32_t mbar) {
    asm volatile(
        "cp.async.bulk.shared::cluster.global.mbarrier::complete_tx::bytes [%0], [%1], %2, [%3];"
        :: "r"(dst), "l"(src), "r"(bytes), "r"(mbar) : "memory");
}
__device__ __forceinline__ void mma16816(float* c, const uint32_t* a, const uint32_t* b) {
    asm volatile(
        "mma.sync.aligned.m16n8k16.row.col.f32.f16.f16.f32 "
        "{%0,%1,%2,%3}, {%4,%5,%6,%7}, {%8,%9}, {%0,%1,%2,%3};"
        : "+f"(c[0]), "+f"(c[1]), "+f"(c[2]), "+f"(c[3])
        : "r"(a[0]), "r"(a[1]), "r"(a[2]), "r"(a[3]), "r"(b[0]), "r"(b[1]));
}
// fast tanh (sm_75+ MUFU.TANH; |err| ~1e-5)
__device__ __forceinline__ float tanh_fast(float x) {
    float y;
    asm("tanh.approx.f32 %0, %1;" : "=f"(y) : "f"(x));
    return y;
}
// sigmoid(x) = 0.5*tanh(x/2) + 0.5
__device__ __forceinline__ float sigmoid_fast(float x) {
    return fmaf(tanh_fast(0.5f * x), 0.5f, 0.5f);
}

// ---------------- pack (merged, fp16) ----------------
__device__ __forceinline__ uint32_t pack2h(float v0, float v1) {
    __half h0 = __float2half_rn(v0);
    __half h1 = __float2half_rn(v1);
    uint16_t u0 = *(uint16_t*)&h0, u1 = *(uint16_t*)&h1;
    return (uint32_t)u0 | ((uint32_t)u1 << 16);
}

__global__ __launch_bounds__(256) void pack_all(
    const float* __restrict__ x,   const float* __restrict__ h,
    const float* __restrict__ Wxi, const float* __restrict__ Wxo,
    const float* __restrict__ Wxf, const float* __restrict__ Wxc,
    const float* __restrict__ Whi, const float* __restrict__ Who,
    const float* __restrict__ Whf, const float* __restrict__ Whc)
{
    if (blockIdx.x < A_PACK_BLOCKS) {
        uint32_t idx = blockIdx.x * 256 + threadIdx.x;
        int lane = idx & 31;
        int m16  = (idx >> 5) & 7;
        int kcq  = (idx >> 8) & 63;
        int mblk = idx >> 14;
        int g = lane >> 2, t = lane & 3;
        int r0 = mblk * 128 + m16 * 16 + g;

#pragma unroll
        for (int u = 0; u < 4; u++) {
            const int kc = kcq + u * 64;
            const int kb = kc * 16;
            const float* src  = (u < 2) ? x : h;          // kb<2048 iff u<2
            const int    col0 = (u < 2) ? kb : kb - IN_;

            const float* p0 = src + (size_t)r0 * 2048 + col0;
            const float* p1 = p0 + (size_t)8 * 2048;
            float2 f00 = *(const float2*)(p0 + 2 * t);
            float2 f01 = *(const float2*)(p0 + 2 * t + 8);
            float2 f10 = *(const float2*)(p1 + 2 * t);
            float2 f11 = *(const float2*)(p1 + 2 * t + 8);

            uint4 out;
            out.x = pack2h(f00.x, f00.y);
            out.y = pack2h(f10.x, f10.y);
            out.z = pack2h(f01.x, f01.y);
            out.w = pack2h(f11.x, f11.y);
            g_A[((size_t)(mblk * 256 + kc) * 8 + m16) * 32 + lane] = out;
        }
    } else {
        // B pack: each thread handles the adjacent n8-pair (2*nh, 2*nh+1)
        // and writes ONE coalesced uint4 per (kc) — full 512B warp stores.
        uint32_t idx = (blockIdx.x - A_PACK_BLOCKS) * 256 + threadIdx.x;
        int lane = idx & 31;
        int nh   = (idx >> 5) & 7;     // n8 pair index 0..7
        int kcq  = (idx >> 8) & 63;
        int nblk = idx >> 14;
        int g = lane >> 2, t = lane & 3;

        // per-pair-member source row + weight matrices
        const float* sx[2];
        const float* sh[2];
        int jv[2];
#pragma unroll
        for (int e = 0; e < 2; e++) {
            const int n8 = 2 * nh + e;
            const int p = nblk * 128 + n8 * 8 + g;
            const int gate = (p >> 3) & 3;
            jv[e] = (p >> 5) * 8 + (p & 7);
            sx[e] = (gate == 0) ? Wxi : (gate == 1) ? Wxo : (gate == 2) ? Wxf : Wxc;
            sh[e] = (gate == 0) ? Whi : (gate == 1) ? Who : (gate == 2) ? Whf : Whc;
        }

#pragma unroll
        for (int u = 0; u < 4; u++) {
            const int kc = kcq + u * 64;
            const int kb = kc * 16;
            const int col0 = (u < 2) ? kb : kb - IN_;

            uint4 out;
#pragma unroll
            for (int e = 0; e < 2; e++) {
                const float* src = (u < 2) ? sx[e] : sh[e];
                const float* pr = src + (size_t)jv[e] * 2048 + col0;
                float2 f0 = *(const float2*)(pr + 2 * t);
                float2 f1 = *(const float2*)(pr + 2 * t + 8);
                if (e == 0) { out.x = pack2h(f0.x, f0.y); out.y = pack2h(f1.x, f1.y); }
                else        { out.z = pack2h(f0.x, f0.y); out.w = pack2h(f1.x, f1.y); }
            }
            // uint4 view of g_B: index ((nblk*256+kc)*8 + nh)*32 + lane
            ((uint4*)g_B)[((size_t)(nblk * 256 + kc) * 8 + nh) * 32 + lane] = out;
        }
    }
}

// ---------------- fused GEMM + LSTM (identical to R12) ----------------
__global__ __launch_bounds__(128, 2) void lstm_gemm_kernel(
    const float* __restrict__ c_prev,
    const float* __restrict__ bi,  const float* __restrict__ bo,
    const float* __restrict__ bfv, const float* __restrict__ bc,
    float* __restrict__ out_h, float* __restrict__ out_c)
{
    extern __shared__ __align__(1024) unsigned char smem_raw[];
    __shared__ __align__(8) uint64_t mbar_full[STAGES];

    const int tid  = threadIdx.x;
    const int wid  = tid >> 5;
    const int lane = tid & 31;
    const int warp_m = wid & 1;     // 2 warps along M (64 rows each)
    const int warp_n = wid >> 1;    // 2 warps along N (64 packed cols each)
    // swapped rasterization: x = mblk (fast), y = nblk
    const int by = blockIdx.x;      // mblk 0..31
    const int bx = blockIdx.y;      // nblk 0..63

    const uint32_t sbase = smem_u32(smem_raw);
    uint32_t full[STAGES];
#pragma unroll
    for (int s = 0; s < STAGES; s++) full[s] = smem_u32(&mbar_full[s]);

    if (tid == 0) {
#pragma unroll
        for (int s = 0; s < STAGES; s++) MBAR_INIT(full[s], 1);
    }
    __syncthreads();

    const uint4* Abase = g_A + (size_t)by * 256 * 8 * 32;
    const uint4* Bbase = (const uint4*)g_B + (size_t)bx * 256 * 8 * 32;

    // prologue: fill stages (chunks 0..2)
    if (tid == 0) {
#pragma unroll
        for (int s = 0; s < STAGES; s++) {
            MBAR_EXPECT_TX(full[s], STAGE_BYTES);
            bulk_cp(sbase + s * STAGE_BYTES,
                    Abase + (size_t)s * 1024, A_STAGE_BYTES, full[s]);
            bulk_cp(sbase + s * STAGE_BYTES + A_STAGE_BYTES,
                    Bbase + (size_t)s * 1024, B_STAGE_BYTES, full[s]);
        }
    }

    float acc[4][8][4];
#pragma unroll
    for (int mm = 0; mm < 4; mm++)
#pragma unroll
        for (int nn = 0; nn < 8; nn++)
#pragma unroll
            for (int q = 0; q < 4; q++) acc[mm][nn][q] = 0.0f;

    for (int i = 0; i < NCHUNK; i++) {
        const int s = i % STAGES;
        const uint32_t ph = (i / STAGES) & 1;
        mbar_wait(full[s], ph);

        const unsigned char* stA = smem_raw + s * STAGE_BYTES;
        const unsigned char* stB = stA + A_STAGE_BYTES;

#pragma unroll
        for (int k16 = 0; k16 < 4; k16++) {
            uint32_t a[4][4];
            uint32_t b[8][2];
#pragma unroll
            for (int mm = 0; mm < 4; mm++) {
                const uint4 v = *(const uint4*)(stA + ((k16 * 8 + warp_m * 4 + mm) * 32 + lane) * 16);
                a[mm][0] = v.x; a[mm][1] = v.y; a[mm][2] = v.z; a[mm][3] = v.w;
            }
#pragma unroll
            for (int np = 0; np < 4; np++) {
                const uint4 v = *(const uint4*)(stB + ((k16 * 8 + warp_n * 4 + np) * 32 + lane) * 16);
                b[np*2+0][0] = v.x; b[np*2+0][1] = v.y;
                b[np*2+1][0] = v.z; b[np*2+1][1] = v.w;
            }
#pragma unroll
            for (int mm = 0; mm < 4; mm++)
#pragma unroll
                for (int nn = 0; nn < 8; nn++)
                    mma16816(acc[mm][nn], a[mm], b[nn]);
        }

        __syncthreads();   // stage s fully consumed by all warps

        if (tid == 0 && i + STAGES < NCHUNK) {
            const int nc = i + STAGES;
            MBAR_EXPECT_TX(full[s], STAGE_BYTES);
            bulk_cp(sbase + s * STAGE_BYTES,
                    Abase + (size_t)nc * 1024, A_STAGE_BYTES, full[s]);
            bulk_cp(sbase + s * STAGE_BYTES + A_STAGE_BYTES,
                    Bbase + (size_t)nc * 1024, B_STAGE_BYTES, full[s]);
        }
    }

    // ---------------- fused LSTM epilogue (MUFU-minimal) ----------------
    const int t = lane & 3, g = lane >> 2;

#pragma unroll
    for (int gg = 0; gg < 2; gg++) {
        const int j0 = (bx * 4 + warp_n * 2 + gg) * 8 + 2 * t;
        const float2 bi2 = *(const float2*)&bi[j0];
        const float2 bo2 = *(const float2*)&bo[j0];
        const float2 bf2 = *(const float2*)&bfv[j0];
        const float2 bc2v = *(const float2*)&bc[j0];

#pragma unroll
        for (int mm = 0; mm < 4; mm++) {
#pragma unroll
            for (int rr = 0; rr < 2; rr++) {
                const int m = by * 128 + warp_m * 64 + mm * 16 + g + rr * 8;
                const size_t base = (size_t)m * H_ + j0;
                const float2 cp = *(const float2*)&c_prev[base];

                float nh[2], ncv[2];
#pragma unroll
                for (int jj = 0; jj < 2; jj++) {
                    const int q = rr * 2 + jj;
                    const float gi = acc[mm][gg*4+0][q] + (jj ? bi2.y : bi2.x);
                    const float go = acc[mm][gg*4+1][q] + (jj ? bo2.y : bo2.x);
                    const float gf = acc[mm][gg*4+2][q] + (jj ? bf2.y : bf2.x);
                    const float gc = acc[mm][gg*4+3][q] + (jj ? bc2v.y : bc2v.x);

                    const float it = sigmoid_fast(gi);
                    const float ot = sigmoid_fast(go);
                    const float ft = sigmoid_fast(gf);
                    const float ct = tanh_fast(gc);

                    const float cold = jj ? cp.y : cp.x;
                    const float nc = ft * cold + it * ct;
                    ncv[jj] = nc;
                    nh[jj]  = ot * tanh_fast(nc);
                }
                *(float2*)&out_c[base] = make_float2(ncv[0], ncv[1]);
                *(float2*)&out_h[base] = make_float2(nh[0], nh[1]);
            }
        }
    }
}

// ---------------- launch ----------------
extern "C" void kernel_launch(void* const* d_in, const int* in_sizes, int n_in,
                              void* d_out, int out_size) {
    const float* x   = (const float*)d_in[0];
    const float* h   = (const float*)d_in[1];
    const float* c   = (const float*)d_in[2];
    const float* Wxi = (const float*)d_in[3];
    const float* Wxo = (const float*)d_in[4];
    const float* Wxf = (const float*)d_in[5];
    const float* Wxc = (const float*)d_in[6];
    const float* bi  = (const float*)d_in[7];
    const float* bo  = (const float*)d_in[8];
    const float* bfv = (const float*)d_in[9];
    const float* bc  = (const float*)d_in[10];
    const float* Whi = (const float*)d_in[11];
    const float* Who = (const float*)d_in[12];
    const float* Whf = (const float*)d_in[13];
    const float* Whc = (const float*)d_in[14];

    float* out   = (float*)d_out;
    float* out_h = out;
    float* out_c = out + (size_t)B_ * H_;

    static bool attr_set = false;
    if (!attr_set) {
        cudaFuncSetAttribute(lstm_gemm_kernel,
                             cudaFuncAttributeMaxDynamicSharedMemorySize, SMEM_REQ);
        attr_set = true;
    }

    pack_all<<<A_PACK_BLOCKS + B_PACK_BLOCKS, 256>>>(x, h,
                                                     Wxi, Wxo, Wxf, Wxc,
                                                     Whi, Who, Whf, Whc);

    dim3 grid(MBLK, NBLK);   // (32, 64): consecutive CTAs share B block, sweep A
    lstm_gemm_kernel<<<grid, 128, SMEM_REQ>>>(c, bi, bo, bfv, bc, out_h, out_c);
}